// round 1
// baseline (speedup 1.0000x reference)
#include <cuda_runtime.h>
#include <cstdint>

// Problem constants (fixed by the dataset)
#define T_TOK 8192
#define G_GRP 8
#define K_DIM 1024
#define N_DIM 2048

// Tiling
constexpr int BM = 128;   // rows (tokens) per tile
constexpr int BN = 64;    // output cols per tile
constexpr int BK = 16;    // k-slice
constexpr int TM = 8;     // per-thread rows
constexpr int TN = 4;     // per-thread cols
constexpr int THREADS = (BM / TM) * (BN / TN);  // 16*16 = 256

__global__ __launch_bounds__(THREADS, 2)
void grouped_gemm_f32_kernel(const float* __restrict__ x,     // [T, K]
                             const float* __restrict__ w,     // [G, N, K]
                             const int*   __restrict__ offs,  // [G] cumulative end offsets
                             float*       __restrict__ out)   // [T, N]
{
    const int g = blockIdx.z;
    const int lo = (g == 0) ? 0 : offs[g - 1];
    const int hi = offs[g];

    const int tile_m0 = blockIdx.y * BM;
    // This (row-tile, group) block only works the intersection of the tile
    // with group g's contiguous row range. Disjoint -> ghost block, exit.
    if (hi <= tile_m0 || lo >= tile_m0 + BM) return;

    const int n0 = blockIdx.x * BN;

    __shared__ float As[BK][BM + 4];  // A transposed: As[k][m]
    __shared__ float Bs[BK][BN + 4];  // Bs[k][n]

    const int tid = threadIdx.x;
    const int tx = tid & 15;   // 0..15 -> n direction
    const int ty = tid >> 4;   // 0..15 -> m direction

    const float* wg = w + (size_t)g * N_DIM * K_DIM;

    float acc[TM][TN];
#pragma unroll
    for (int i = 0; i < TM; i++)
#pragma unroll
        for (int j = 0; j < TN; j++) acc[i][j] = 0.0f;

    // A-tile load mapping: 128x16 floats = 2048 = 256 thr * 8 floats = 2 float4/thr
    //   flat f = tid*8 ; row = tid>>1 ; col = (tid&1)*8 + {0,4}
    const int ar = tid >> 1;
    const int ac = (tid & 1) * 8;
    // B-tile load mapping: 64x16 floats = 1024 = 256 thr * 4 floats = 1 float4/thr
    //   n = tid>>2 ; k = (tid&3)*4
    const int bn = tid >> 2;
    const int bk = (tid & 3) * 4;

    const float* a_ptr = x + (size_t)(tile_m0 + ar) * K_DIM + ac;
    const float* b_ptr = wg + (size_t)(n0 + bn) * K_DIM + bk;

    for (int k0 = 0; k0 < K_DIM; k0 += BK) {
        // Prefetch to registers (rows may be outside the clip range; memory is
        // still valid — results for those rows are simply never stored).
        const float4 a0 = *(const float4*)(a_ptr + k0);
        const float4 a1 = *(const float4*)(a_ptr + k0 + 4);
        const float4 b0 = *(const float4*)(b_ptr + k0);

        __syncthreads();  // previous iteration's consumers done with smem

        As[ac + 0][ar] = a0.x;
        As[ac + 1][ar] = a0.y;
        As[ac + 2][ar] = a0.z;
        As[ac + 3][ar] = a0.w;
        As[ac + 4][ar] = a1.x;
        As[ac + 5][ar] = a1.y;
        As[ac + 6][ar] = a1.z;
        As[ac + 7][ar] = a1.w;

        Bs[bk + 0][bn] = b0.x;
        Bs[bk + 1][bn] = b0.y;
        Bs[bk + 2][bn] = b0.z;
        Bs[bk + 3][bn] = b0.w;

        __syncthreads();  // tile visible to all

#pragma unroll
        for (int kk = 0; kk < BK; kk++) {
            float a_frag[TM];
            float b_frag[TN];
            *(float4*)&a_frag[0] = *(const float4*)&As[kk][ty * TM];
            *(float4*)&a_frag[4] = *(const float4*)&As[kk][ty * TM + 4];
            *(float4*)&b_frag[0] = *(const float4*)&Bs[kk][tx * TN];
#pragma unroll
            for (int i = 0; i < TM; i++)
#pragma unroll
                for (int j = 0; j < TN; j++)
                    acc[i][j] = fmaf(a_frag[i], b_frag[j], acc[i][j]);
        }
    }

    // Store only rows inside [lo, hi): exactly-once coverage across groups.
#pragma unroll
    for (int i = 0; i < TM; i++) {
        const int r = tile_m0 + ty * TM + i;
        if (r >= lo && r < hi) {
            float4 v;
            v.x = acc[i][0];
            v.y = acc[i][1];
            v.z = acc[i][2];
            v.w = acc[i][3];
            *(float4*)&out[(size_t)r * N_DIM + n0 + tx * TN] = v;
        }
    }
}

extern "C" void kernel_launch(void* const* d_in, const int* in_sizes, int n_in,
                              void* d_out, int out_size) {
    const float* x    = (const float*)d_in[0];  // [T, K] fp32
    const float* w    = (const float*)d_in[1];  // [G, N, K] fp32
    const int*   offs = (const int*)d_in[2];    // [G] int32
    float* out = (float*)d_out;                 // [T, N] fp32

    dim3 grid(N_DIM / BN, T_TOK / BM, G_GRP);   // 32 x 64 x 8
    dim3 block(THREADS);
    grouped_gemm_f32_kernel<<<grid, block>>>(x, w, offs, out);
}

// round 3
// speedup vs baseline: 2.5803x; 2.5803x over previous
#include <cuda_runtime.h>
#include <cuda_bf16.h>
#include <cstdint>

// ---------------- problem constants ----------------
#define T_TOK 8192
#define G_GRP 8
#define K_DIM 1024
#define N_DIM 2048
#define KC    2048   // concatenated hi|lo K in scratch

// ---------------- scratch (bf16 hi|lo) ----------------
__device__ __nv_bfloat16 g_xc[(size_t)T_TOK * KC];            // [T, 2048]
__device__ __nv_bfloat16 g_wc[(size_t)G_GRP * N_DIM * KC];    // [G*N, 2048]

// ---------------- conversion kernel ----------------
// src rows of 1024 fp32 -> dst rows of 2048 bf16: cols [0,1024)=hi, [1024,2048)=lo
__global__ void convert_hilo(const float* __restrict__ src,
                             __nv_bfloat16* __restrict__ dst, int nrows)
{
    size_t i = (size_t)blockIdx.x * blockDim.x + threadIdx.x;  // one float4
    size_t total = (size_t)nrows * (K_DIM / 4);
    if (i >= total) return;
    size_t row = i / (K_DIM / 4);
    size_t c4  = (i - row * (K_DIM / 4)) * 4;
    float4 v = reinterpret_cast<const float4*>(src)[i];
    float f[4] = {v.x, v.y, v.z, v.w};
    union { __nv_bfloat16 b[4]; uint2 u; } H, L;
#pragma unroll
    for (int j = 0; j < 4; j++) {
        __nv_bfloat16 h = __float2bfloat16_rn(f[j]);
        H.b[j] = h;
        L.b[j] = __float2bfloat16_rn(f[j] - __bfloat162float(h));
    }
    __nv_bfloat16* base = dst + row * KC;
    *reinterpret_cast<uint2*>(base + c4)         = H.u;
    *reinterpret_cast<uint2*>(base + K_DIM + c4) = L.u;
}

// ---------------- PTX helpers (baseline features only) ----------------
__device__ __forceinline__ uint32_t smem_u32(const void* p) {
    uint32_t a;
    asm("{ .reg .u64 t; cvta.to.shared.u64 t, %1; cvt.u32.u64 %0, t; }"
        : "=r"(a) : "l"(p));
    return a;
}
__device__ __forceinline__ void cp16(uint32_t dst, const void* src) {
    asm volatile("cp.async.cg.shared.global [%0], [%1], 16;" :: "r"(dst), "l"(src));
}
#define CP_COMMIT() asm volatile("cp.async.commit_group;" ::: "memory")
#define CP_WAIT1()  asm volatile("cp.async.wait_group 1;" ::: "memory")

__device__ __forceinline__ void ldsm_x4(uint32_t& r0, uint32_t& r1,
                                        uint32_t& r2, uint32_t& r3, uint32_t a) {
    asm volatile("ldmatrix.sync.aligned.m8n8.x4.shared.b16 {%0,%1,%2,%3}, [%4];"
                 : "=r"(r0), "=r"(r1), "=r"(r2), "=r"(r3) : "r"(a));
}
__device__ __forceinline__ void ldsm_x2(uint32_t& r0, uint32_t& r1, uint32_t a) {
    asm volatile("ldmatrix.sync.aligned.m8n8.x2.shared.b16 {%0,%1}, [%2];"
                 : "=r"(r0), "=r"(r1) : "r"(a));
}
__device__ __forceinline__ void mma_16816(float* c, const uint32_t* a,
                                          const uint32_t* b) {
    asm volatile(
        "mma.sync.aligned.m16n8k16.row.col.f32.bf16.bf16.f32 "
        "{%0,%1,%2,%3}, {%4,%5,%6,%7}, {%8,%9}, {%0,%1,%2,%3};"
        : "+f"(c[0]), "+f"(c[1]), "+f"(c[2]), "+f"(c[3])
        : "r"(a[0]), "r"(a[1]), "r"(a[2]), "r"(a[3]), "r"(b[0]), "r"(b[1]));
}

// ---------------- GEMM kernel ----------------
constexpr int BM = 128, BN = 128, BK = 64;
constexpr int STAGES = 3;
constexpr int A_BYTES = BM * BK * 2;            // 16384
constexpr int B_BYTES = BN * BK * 2;            // 16384
constexpr int STAGE_BYTES = A_BYTES + B_BYTES;  // 32768
constexpr int SMEM_TOTAL = STAGES * STAGE_BYTES;  // 98304
constexpr int NITER = 3 * (K_DIM / BK);         // 48 (3 hi/lo passes)

// sw128 swizzle for 128-byte rows: 16B chunk c at row r lands at chunk c^(r&7)
__device__ __forceinline__ uint32_t swz(uint32_t row, uint32_t chunk) {
    return row * 128u + ((chunk ^ (row & 7u)) << 4);
}

__global__ __launch_bounds__(256)
void grouped_gemm_hmma(const int* __restrict__ offs, float* __restrict__ out)
{
    const int g = blockIdx.z;
    const int lo = (g == 0) ? 0 : __ldg(offs + g - 1);
    const int hi = __ldg(offs + g);
    const int m0 = blockIdx.y * BM;
    if (hi <= m0 || lo >= m0 + BM) return;   // ghost block
    const int n0 = blockIdx.x * BN;

    extern __shared__ __align__(1024) char smem[];
    const uint32_t sb = smem_u32(smem);

    const int tid  = threadIdx.x;
    const int wid  = tid >> 5;
    const int lane = tid & 31;

    // warp grid 2 (m) x 4 (n): warp tile 64x32
    const int WM0 = (wid >> 2) * 64;
    const int WN0 = (wid & 3) * 32;

    // ---- cp.async mapping: 1024 16B-chunks per operand, 4 per thread ----
    // chunk q = tid + 256*j  -> row = q>>3, c = q&7
    const int c8 = tid & 7;          // chunk within row
    const int r0 = tid >> 3;         // base row (j adds 32)
    const __nv_bfloat16* aG = g_xc + (size_t)(m0 + r0) * KC + c8 * 8;
    const __nv_bfloat16* bG = g_wc + ((size_t)g * N_DIM + n0 + r0) * KC + c8 * 8;

    auto load_stage = [&](int s) {
        const int p = s / (K_DIM / BK);          // pass 0,1,2
        const int kb = (s % (K_DIM / BK)) * BK;  // k base within 1024
        const int acol = ((p == 1) ? K_DIM : 0) + kb;   // pass1: x_lo
        const int bcol = ((p == 2) ? K_DIM : 0) + kb;   // pass2: w_lo
        const uint32_t base = sb + (uint32_t)(s % STAGES) * STAGE_BYTES;
#pragma unroll
        for (int j = 0; j < 4; j++) {
            const uint32_t row = (uint32_t)r0 + 32u * j;
            cp16(base + swz(row, c8), aG + (size_t)(32 * j) * KC + acol);
            cp16(base + A_BYTES + swz(row, c8), bG + (size_t)(32 * j) * KC + bcol);
        }
    };

    float acc[4][4][4];
#pragma unroll
    for (int i = 0; i < 4; i++)
#pragma unroll
        for (int j = 0; j < 4; j++)
#pragma unroll
            for (int q = 0; q < 4; q++) acc[i][j][q] = 0.0f;

    load_stage(0); CP_COMMIT();
    load_stage(1); CP_COMMIT();

    for (int it = 0; it < NITER; it++) {
        CP_WAIT1();          // stage `it` resident
        __syncthreads();     // all warps past compute of it-1 (frees buf (it+2)%3)

        if (it + 2 < NITER) load_stage(it + 2);
        CP_COMMIT();         // unconditional: keeps group counting uniform

        const uint32_t aS = sb + (uint32_t)(it % STAGES) * STAGE_BYTES;
        const uint32_t bS = aS + A_BYTES;

#pragma unroll
        for (int ks = 0; ks < BK / 16; ks++) {   // 4 k16 steps
            const uint32_t cA = 2u * ks;
            uint32_t a[4][4], b[4][2];
#pragma unroll
            for (int i = 0; i < 4; i++) {
                const uint32_t row = (uint32_t)(WM0 + i * 16 + (lane & 15));
                const uint32_t ch  = cA + (uint32_t)(lane >> 4);
                ldsm_x4(a[i][0], a[i][1], a[i][2], a[i][3], aS + swz(row, ch));
            }
#pragma unroll
            for (int j = 0; j < 4; j++) {
                const uint32_t row = (uint32_t)(WN0 + j * 8 + (lane & 7));
                const uint32_t ch  = cA + ((uint32_t)(lane >> 3) & 1u);
                ldsm_x2(b[j][0], b[j][1], bS + swz(row, ch));
            }
#pragma unroll
            for (int i = 0; i < 4; i++)
#pragma unroll
                for (int j = 0; j < 4; j++)
                    mma_16816(acc[i][j], a[i], b[j]);
        }
    }

    // ---- epilogue: direct fp32 stores with group row-clipping ----
    const int rbase = m0 + WM0 + (lane >> 2);
    const int cbase = n0 + WN0 + (lane & 3) * 2;
#pragma unroll
    for (int i = 0; i < 4; i++) {
        const int ra = rbase + i * 16;
        const int rb = ra + 8;
        const bool wa = (ra >= lo && ra < hi);
        const bool wb = (rb >= lo && rb < hi);
        float* pa = out + (size_t)ra * N_DIM + cbase;
        float* pb = out + (size_t)rb * N_DIM + cbase;
#pragma unroll
        for (int j = 0; j < 4; j++) {
            if (wa) *reinterpret_cast<float2*>(pa + j * 8) =
                make_float2(acc[i][j][0], acc[i][j][1]);
            if (wb) *reinterpret_cast<float2*>(pb + j * 8) =
                make_float2(acc[i][j][2], acc[i][j][3]);
        }
    }
}

// ---------------- launch ----------------
extern "C" void kernel_launch(void* const* d_in, const int* in_sizes, int n_in,
                              void* d_out, int out_size) {
    const float* x    = (const float*)d_in[0];  // [T, K]
    const float* w    = (const float*)d_in[1];  // [G, N, K]
    const int*   offs = (const int*)d_in[2];    // [G]
    float* out = (float*)d_out;                 // [T, N]

    __nv_bfloat16 *xc_ptr, *wc_ptr;
    cudaGetSymbolAddress((void**)&xc_ptr, g_xc);
    cudaGetSymbolAddress((void**)&wc_ptr, g_wc);

    {
        int threads = 256;
        int blocksX = (T_TOK * (K_DIM / 4) + threads - 1) / threads;
        convert_hilo<<<blocksX, threads>>>(x, xc_ptr, T_TOK);
        int blocksW = (G_GRP * N_DIM * (K_DIM / 4) + threads - 1) / threads;
        convert_hilo<<<blocksW, threads>>>(w, wc_ptr, G_GRP * N_DIM);
    }

    cudaFuncSetAttribute(grouped_gemm_hmma,
                         cudaFuncAttributeMaxDynamicSharedMemorySize, SMEM_TOTAL);
    dim3 grid(N_DIM / BN, T_TOK / BM, G_GRP);   // 16 x 64 x 8
    grouped_gemm_hmma<<<grid, 256, SMEM_TOTAL>>>(offs, out);
}

// round 4
// speedup vs baseline: 2.7357x; 1.0603x over previous
#include <cuda_runtime.h>
#include <cuda_bf16.h>
#include <cstdint>

// ---------------- problem constants ----------------
#define T_TOK 8192
#define G_GRP 8
#define K_DIM 1024
#define N_DIM 2048
#define KC    2048   // concatenated hi|lo K in scratch

// ---------------- scratch (bf16 hi|lo) ----------------
__device__ __nv_bfloat16 g_xc[(size_t)T_TOK * KC];            // [T, 2048]
__device__ __nv_bfloat16 g_wc[(size_t)G_GRP * N_DIM * KC];    // [G*N, 2048]

// ---------------- conversion kernel ----------------
__global__ void convert_hilo(const float* __restrict__ src,
                             __nv_bfloat16* __restrict__ dst, int nrows)
{
    size_t i = (size_t)blockIdx.x * blockDim.x + threadIdx.x;  // one float4
    size_t total = (size_t)nrows * (K_DIM / 4);
    if (i >= total) return;
    size_t row = i / (K_DIM / 4);
    size_t c4  = (i - row * (K_DIM / 4)) * 4;
    float4 v = reinterpret_cast<const float4*>(src)[i];
    float f[4] = {v.x, v.y, v.z, v.w};
    union { __nv_bfloat16 b[4]; uint2 u; } H, L;
#pragma unroll
    for (int j = 0; j < 4; j++) {
        __nv_bfloat16 h = __float2bfloat16_rn(f[j]);
        H.b[j] = h;
        L.b[j] = __float2bfloat16_rn(f[j] - __bfloat162float(h));
    }
    __nv_bfloat16* base = dst + row * KC;
    *reinterpret_cast<uint2*>(base + c4)         = H.u;
    *reinterpret_cast<uint2*>(base + K_DIM + c4) = L.u;
}

// ---------------- PTX helpers (baseline features only) ----------------
__device__ __forceinline__ uint32_t smem_u32(const void* p) {
    uint32_t a;
    asm("{ .reg .u64 t; cvta.to.shared.u64 t, %1; cvt.u32.u64 %0, t; }"
        : "=r"(a) : "l"(p));
    return a;
}
__device__ __forceinline__ void cp16(uint32_t dst, const void* src) {
    asm volatile("cp.async.cg.shared.global [%0], [%1], 16;" :: "r"(dst), "l"(src));
}
#define CP_COMMIT() asm volatile("cp.async.commit_group;" ::: "memory")
#define CP_WAIT1()  asm volatile("cp.async.wait_group 1;" ::: "memory")

__device__ __forceinline__ void ldsm_x4(uint32_t& r0, uint32_t& r1,
                                        uint32_t& r2, uint32_t& r3, uint32_t a) {
    asm volatile("ldmatrix.sync.aligned.m8n8.x4.shared.b16 {%0,%1,%2,%3}, [%4];"
                 : "=r"(r0), "=r"(r1), "=r"(r2), "=r"(r3) : "r"(a));
}
__device__ __forceinline__ void mma_16816(float* c, const uint32_t* a,
                                          const uint32_t* b) {
    asm volatile(
        "mma.sync.aligned.m16n8k16.row.col.f32.bf16.bf16.f32 "
        "{%0,%1,%2,%3}, {%4,%5,%6,%7}, {%8,%9}, {%0,%1,%2,%3};"
        : "+f"(c[0]), "+f"(c[1]), "+f"(c[2]), "+f"(c[3])
        : "r"(a[0]), "r"(a[1]), "r"(a[2]), "r"(a[3]), "r"(b[0]), "r"(b[1]));
}

// ---------------- GEMM kernel ----------------
constexpr int BM = 128, BN = 128, BK = 64;
constexpr int STAGES = 3;
constexpr int PLANE = BM * BK * 2;              // 16384 bytes per operand plane
constexpr int STAGE_BYTES = 4 * PLANE;          // AH | AL | BH | BL = 65536
constexpr int SMEM_TOTAL = STAGES * STAGE_BYTES;  // 196608
constexpr int NITER = K_DIM / BK;               // 16 (single fused K sweep)

// sw128 swizzle for 128-byte rows: 16B chunk c at row r lands at chunk c^(r&7)
__device__ __forceinline__ uint32_t swz(uint32_t row, uint32_t chunk) {
    return row * 128u + ((chunk ^ (row & 7u)) << 4);
}

__global__ __launch_bounds__(256)
void grouped_gemm_hmma(const int* __restrict__ offs, float* __restrict__ out)
{
    const int g = blockIdx.z;
    const int lo = (g == 0) ? 0 : __ldg(offs + g - 1);
    const int hi = __ldg(offs + g);
    const int m0 = blockIdx.y * BM;
    if (hi <= m0 || lo >= m0 + BM) return;   // ghost block
    const int n0 = blockIdx.x * BN;

    extern __shared__ __align__(1024) char smem[];
    const uint32_t sb = smem_u32(smem);

    const int tid  = threadIdx.x;
    const int wid  = tid >> 5;
    const int lane = tid & 31;

    // warp grid 2 (m) x 4 (n): warp tile 64x32
    const int WM0 = (wid >> 2) * 64;
    const int WN0 = (wid & 3) * 32;

    // ---- cp.async mapping: per plane 1024 16B-chunks, 4/thread (rows r0+32j)
    const int c8 = tid & 7;
    const int r0 = tid >> 3;
    const __nv_bfloat16* aG = g_xc + (size_t)(m0 + r0) * KC + c8 * 8;
    const __nv_bfloat16* bG = g_wc + ((size_t)g * N_DIM + n0 + r0) * KC + c8 * 8;

    auto load_stage = [&](int s) {
        const int kb = s * BK;                  // k base within [0,1024)
        const uint32_t base = sb + (uint32_t)(s % STAGES) * STAGE_BYTES;
#pragma unroll
        for (int j = 0; j < 4; j++) {
            const uint32_t row = (uint32_t)r0 + 32u * j;
            const uint32_t so  = swz(row, c8);
            const __nv_bfloat16* ap = aG + (size_t)(32 * j) * KC;
            const __nv_bfloat16* bp = bG + (size_t)(32 * j) * KC;
            cp16(base + 0 * PLANE + so, ap + kb);            // A_hi
            cp16(base + 1 * PLANE + so, ap + K_DIM + kb);    // A_lo
            cp16(base + 2 * PLANE + so, bp + kb);            // B_hi
            cp16(base + 3 * PLANE + so, bp + K_DIM + kb);    // B_lo
        }
    };

    float acc[4][4][4];
#pragma unroll
    for (int i = 0; i < 4; i++)
#pragma unroll
        for (int j = 0; j < 4; j++)
#pragma unroll
            for (int q = 0; q < 4; q++) acc[i][j][q] = 0.0f;

    load_stage(0); CP_COMMIT();
    load_stage(1); CP_COMMIT();

    for (int it = 0; it < NITER; it++) {
        CP_WAIT1();          // stage `it` resident
        __syncthreads();     // all warps finished with buf (it+2)%3 (= it-1)

        if (it + 2 < NITER) load_stage(it + 2);
        CP_COMMIT();         // unconditional: uniform group counting

        const uint32_t st = sb + (uint32_t)(it % STAGES) * STAGE_BYTES;
        const uint32_t aH = st, aL = st + PLANE, bH = st + 2 * PLANE, bL = st + 3 * PLANE;

#pragma unroll
        for (int ks = 0; ks < BK / 16; ks++) {   // 4 k16 steps
            const uint32_t cA = 2u * ks;
            uint32_t ah[4][4], al[4][4], bh[4][2], bl[4][2];
            // A fragments (64 rows, hi+lo)
#pragma unroll
            for (int i = 0; i < 4; i++) {
                const uint32_t row = (uint32_t)(WM0 + i * 16 + (lane & 15));
                const uint32_t so  = swz(row, cA + (uint32_t)(lane >> 4));
                ldsm_x4(ah[i][0], ah[i][1], ah[i][2], ah[i][3], aH + so);
                ldsm_x4(al[i][0], al[i][1], al[i][2], al[i][3], aL + so);
            }
            // B fragments: x4 covers a j-pair (16 n rows x both k chunks)
#pragma unroll
            for (int jp = 0; jp < 2; jp++) {
                const uint32_t row = (uint32_t)(WN0 + (jp * 2 + ((lane >> 4) & 1)) * 8
                                                + (lane & 7));
                const uint32_t so  = swz(row, cA + ((uint32_t)(lane >> 3) & 1u));
                ldsm_x4(bh[jp * 2][0], bh[jp * 2][1],
                        bh[jp * 2 + 1][0], bh[jp * 2 + 1][1], bH + so);
                ldsm_x4(bl[jp * 2][0], bl[jp * 2][1],
                        bl[jp * 2 + 1][0], bl[jp * 2 + 1][1], bL + so);
            }
            // 3 products per fragment set: hi*hi + lo*hi + hi*lo
#pragma unroll
            for (int i = 0; i < 4; i++)
#pragma unroll
                for (int j = 0; j < 4; j++) {
                    mma_16816(acc[i][j], ah[i], bh[j]);
                    mma_16816(acc[i][j], al[i], bh[j]);
                    mma_16816(acc[i][j], ah[i], bl[j]);
                }
        }
    }

    // ---- epilogue: direct fp32 stores with group row-clipping ----
    const int rbase = m0 + WM0 + (lane >> 2);
    const int cbase = n0 + WN0 + (lane & 3) * 2;
#pragma unroll
    for (int i = 0; i < 4; i++) {
        const int ra = rbase + i * 16;
        const int rb = ra + 8;
        const bool wa = (ra >= lo && ra < hi);
        const bool wb = (rb >= lo && rb < hi);
        float* pa = out + (size_t)ra * N_DIM + cbase;
        float* pb = out + (size_t)rb * N_DIM + cbase;
#pragma unroll
        for (int j = 0; j < 4; j++) {
            if (wa) *reinterpret_cast<float2*>(pa + j * 8) =
                make_float2(acc[i][j][0], acc[i][j][1]);
            if (wb) *reinterpret_cast<float2*>(pb + j * 8) =
                make_float2(acc[i][j][2], acc[i][j][3]);
        }
    }
}

// ---------------- launch ----------------
extern "C" void kernel_launch(void* const* d_in, const int* in_sizes, int n_in,
                              void* d_out, int out_size) {
    const float* x    = (const float*)d_in[0];  // [T, K]
    const float* w    = (const float*)d_in[1];  // [G, N, K]
    const int*   offs = (const int*)d_in[2];    // [G]
    float* out = (float*)d_out;                 // [T, N]

    __nv_bfloat16 *xc_ptr, *wc_ptr;
    cudaGetSymbolAddress((void**)&xc_ptr, g_xc);
    cudaGetSymbolAddress((void**)&wc_ptr, g_wc);

    {
        int threads = 256;
        int blocksX = (T_TOK * (K_DIM / 4) + threads - 1) / threads;
        convert_hilo<<<blocksX, threads>>>(x, xc_ptr, T_TOK);
        int blocksW = (G_GRP * N_DIM * (K_DIM / 4) + threads - 1) / threads;
        convert_hilo<<<blocksW, threads>>>(w, wc_ptr, G_GRP * N_DIM);
    }

    cudaFuncSetAttribute(grouped_gemm_hmma,
                         cudaFuncAttributeMaxDynamicSharedMemorySize, SMEM_TOTAL);
    dim3 grid(N_DIM / BN, T_TOK / BM, G_GRP);   // 16 x 64 x 8
    grouped_gemm_hmma<<<grid, 256, SMEM_TOTAL>>>(offs, out);
}

// round 5
// speedup vs baseline: 2.7788x; 1.0157x over previous
#include <cuda_runtime.h>
#include <cuda_bf16.h>
#include <cstdint>

// ---------------- problem constants ----------------
#define T_TOK 8192
#define G_GRP 8
#define K_DIM 1024
#define N_DIM 2048
#define KC    2048   // concatenated hi|lo K in scratch

// ---------------- scratch (bf16 hi|lo) ----------------
__device__ __nv_bfloat16 g_xc[(size_t)T_TOK * KC];            // [T, 2048]
__device__ __nv_bfloat16 g_wc[(size_t)G_GRP * N_DIM * KC];    // [G*N, 2048]

// ---------------- conversion kernel ----------------
__global__ void convert_hilo(const float* __restrict__ src,
                             __nv_bfloat16* __restrict__ dst, int nrows)
{
    size_t i = (size_t)blockIdx.x * blockDim.x + threadIdx.x;  // one float4
    size_t total = (size_t)nrows * (K_DIM / 4);
    if (i >= total) return;
    size_t row = i / (K_DIM / 4);
    size_t c4  = (i - row * (K_DIM / 4)) * 4;
    float4 v = reinterpret_cast<const float4*>(src)[i];
    float f[4] = {v.x, v.y, v.z, v.w};
    union { __nv_bfloat16 b[4]; uint2 u; } H, L;
#pragma unroll
    for (int j = 0; j < 4; j++) {
        __nv_bfloat16 h = __float2bfloat16_rn(f[j]);
        H.b[j] = h;
        L.b[j] = __float2bfloat16_rn(f[j] - __bfloat162float(h));
    }
    __nv_bfloat16* base = dst + row * KC;
    *reinterpret_cast<uint2*>(base + c4)         = H.u;
    *reinterpret_cast<uint2*>(base + K_DIM + c4) = L.u;
}

// ---------------- PTX helpers (baseline features only) ----------------
__device__ __forceinline__ uint32_t smem_u32(const void* p) {
    uint32_t a;
    asm("{ .reg .u64 t; cvta.to.shared.u64 t, %1; cvt.u32.u64 %0, t; }"
        : "=r"(a) : "l"(p));
    return a;
}
__device__ __forceinline__ void cp16(uint32_t dst, const void* src) {
    asm volatile("cp.async.cg.shared.global [%0], [%1], 16;" :: "r"(dst), "l"(src));
}
#define CP_COMMIT() asm volatile("cp.async.commit_group;" ::: "memory")
#define CP_WAIT1()  asm volatile("cp.async.wait_group 1;" ::: "memory")

__device__ __forceinline__ void ldsm_x4(uint32_t& r0, uint32_t& r1,
                                        uint32_t& r2, uint32_t& r3, uint32_t a) {
    asm volatile("ldmatrix.sync.aligned.m8n8.x4.shared.b16 {%0,%1,%2,%3}, [%4];"
                 : "=r"(r0), "=r"(r1), "=r"(r2), "=r"(r3) : "r"(a));
}
__device__ __forceinline__ void mma_16816(float* c, const uint32_t* a,
                                          const uint32_t* b) {
    asm volatile(
        "mma.sync.aligned.m16n8k16.row.col.f32.bf16.bf16.f32 "
        "{%0,%1,%2,%3}, {%4,%5,%6,%7}, {%8,%9}, {%0,%1,%2,%3};"
        : "+f"(c[0]), "+f"(c[1]), "+f"(c[2]), "+f"(c[3])
        : "r"(a[0]), "r"(a[1]), "r"(a[2]), "r"(a[3]), "r"(b[0]), "r"(b[1]));
}

// ---------------- GEMM kernel ----------------
// Smem tile layout: each 128-byte row packs [hi k0..31 | lo k0..31] for one
// matrix row. A tile = 128 rows = 16KB; B tile = 16KB. Stage = 32KB.
constexpr int BM = 128, BN = 128, BK = 32;
constexpr int TILE = BM * 128;                   // 16384 bytes (hi+lo packed)
constexpr int STAGE_BYTES = 2 * TILE;            // A | B = 32768
constexpr int STAGES = 3;
constexpr int SMEM_TOTAL = STAGES * STAGE_BYTES; // 98304 -> 2 CTAs/SM
constexpr int NITER = K_DIM / BK;                // 32

// sw128 swizzle for 128-byte rows: 16B chunk c at row r lands at chunk c^(r&7)
__device__ __forceinline__ uint32_t swz(uint32_t row, uint32_t chunk) {
    return row * 128u + ((chunk ^ (row & 7u)) << 4);
}

__global__ __launch_bounds__(256, 2)
void grouped_gemm_hmma(const int* __restrict__ offs, float* __restrict__ out)
{
    const int g = blockIdx.z;
    const int lo = (g == 0) ? 0 : __ldg(offs + g - 1);
    const int hi = __ldg(offs + g);
    const int m0 = blockIdx.y * BM;
    if (hi <= m0 || lo >= m0 + BM) return;   // ghost block
    const int n0 = blockIdx.x * BN;

    extern __shared__ __align__(1024) char smem[];
    const uint32_t sb = smem_u32(smem);

    const int tid  = threadIdx.x;
    const int wid  = tid >> 5;
    const int lane = tid & 31;

    // warp grid 2 (m) x 4 (n): warp tile 64x32
    const int WM0 = (wid >> 2) * 64;
    const int WN0 = (wid & 3) * 32;

    // ---- cp.async mapping ----
    // Per tile: 128 rows x 8 chunks = 1024 chunks; A+B = 2048 = 8/thread.
    // chunk c8 in row: c8<4 -> hi plane (k = c8*8), c8>=4 -> lo plane.
    const int c8 = tid & 7;
    const int r0 = tid >> 3;
    const int colOff = (c8 < 4) ? c8 * 8 : (K_DIM + (c8 - 4) * 8);
    const __nv_bfloat16* aG = g_xc + (size_t)(m0 + r0) * KC + colOff;
    const __nv_bfloat16* bG = g_wc + ((size_t)g * N_DIM + n0 + r0) * KC + colOff;

    auto load_stage = [&](int s) {
        const int kb = s * BK;
        const uint32_t base = sb + (uint32_t)(s % STAGES) * STAGE_BYTES;
#pragma unroll
        for (int j = 0; j < 4; j++) {
            const uint32_t row = (uint32_t)r0 + 32u * j;
            const uint32_t so  = swz(row, c8);
            cp16(base + so,        aG + (size_t)(32 * j) * KC + kb);
            cp16(base + TILE + so, bG + (size_t)(32 * j) * KC + kb);
        }
    };

    float acc[4][4][4];
#pragma unroll
    for (int i = 0; i < 4; i++)
#pragma unroll
        for (int j = 0; j < 4; j++)
#pragma unroll
            for (int q = 0; q < 4; q++) acc[i][j][q] = 0.0f;

    load_stage(0); CP_COMMIT();
    load_stage(1); CP_COMMIT();

    for (int it = 0; it < NITER; it++) {
        CP_WAIT1();          // stage `it` resident
        __syncthreads();     // all warps finished with buf (it+2)%3 (= it-1)

        if (it + 2 < NITER) load_stage(it + 2);
        CP_COMMIT();         // unconditional: uniform group counting

        const uint32_t aT = sb + (uint32_t)(it % STAGES) * STAGE_BYTES;
        const uint32_t bT = aT + TILE;

#pragma unroll
        for (int ks = 0; ks < BK / 16; ks++) {   // 2 k16 steps
            const uint32_t cHi = 2u * ks;        // hi chunks 0..3
            const uint32_t cLo = cHi + 4u;       // lo chunks 4..7
            uint32_t ah[4][4], al[4][4], bh[4][2], bl[4][2];
            // A fragments (64 rows, hi+lo)
#pragma unroll
            for (int i = 0; i < 4; i++) {
                const uint32_t row = (uint32_t)(WM0 + i * 16 + (lane & 15));
                const uint32_t k2  = (uint32_t)(lane >> 4);
                ldsm_x4(ah[i][0], ah[i][1], ah[i][2], ah[i][3], aT + swz(row, cHi + k2));
                ldsm_x4(al[i][0], al[i][1], al[i][2], al[i][3], aT + swz(row, cLo + k2));
            }
            // B fragments: x4 covers a j-pair (16 n rows x both k chunks)
#pragma unroll
            for (int jp = 0; jp < 2; jp++) {
                const uint32_t row = (uint32_t)(WN0 + (jp * 2 + ((lane >> 4) & 1)) * 8
                                                + (lane & 7));
                const uint32_t k2  = ((uint32_t)(lane >> 3) & 1u);
                const uint32_t soH = swz(row, cHi + k2);
                const uint32_t soL = swz(row, cLo + k2);
                ldsm_x4(bh[jp * 2][0], bh[jp * 2][1],
                        bh[jp * 2 + 1][0], bh[jp * 2 + 1][1], bT + soH);
                ldsm_x4(bl[jp * 2][0], bl[jp * 2][1],
                        bl[jp * 2 + 1][0], bl[jp * 2 + 1][1], bT + soL);
            }
            // 3 products per fragment set: hi*hi + lo*hi + hi*lo
#pragma unroll
            for (int i = 0; i < 4; i++)
#pragma unroll
                for (int j = 0; j < 4; j++) {
                    mma_16816(acc[i][j], ah[i], bh[j]);
                    mma_16816(acc[i][j], al[i], bh[j]);
                    mma_16816(acc[i][j], ah[i], bl[j]);
                }
        }
    }

    // ---- epilogue: direct fp32 stores with group row-clipping ----
    const int rbase = m0 + WM0 + (lane >> 2);
    const int cbase = n0 + WN0 + (lane & 3) * 2;
#pragma unroll
    for (int i = 0; i < 4; i++) {
        const int ra = rbase + i * 16;
        const int rb = ra + 8;
        const bool wa = (ra >= lo && ra < hi);
        const bool wb = (rb >= lo && rb < hi);
        float* pa = out + (size_t)ra * N_DIM + cbase;
        float* pb = out + (size_t)rb * N_DIM + cbase;
#pragma unroll
        for (int j = 0; j < 4; j++) {
            if (wa) *reinterpret_cast<float2*>(pa + j * 8) =
                make_float2(acc[i][j][0], acc[i][j][1]);
            if (wb) *reinterpret_cast<float2*>(pb + j * 8) =
                make_float2(acc[i][j][2], acc[i][j][3]);
        }
    }
}

// ---------------- launch ----------------
extern "C" void kernel_launch(void* const* d_in, const int* in_sizes, int n_in,
                              void* d_out, int out_size) {
    const float* x    = (const float*)d_in[0];  // [T, K]
    const float* w    = (const float*)d_in[1];  // [G, N, K]
    const int*   offs = (const int*)d_in[2];    // [G]
    float* out = (float*)d_out;                 // [T, N]

    __nv_bfloat16 *xc_ptr, *wc_ptr;
    cudaGetSymbolAddress((void**)&xc_ptr, g_xc);
    cudaGetSymbolAddress((void**)&wc_ptr, g_wc);

    {
        int threads = 256;
        int blocksX = (T_TOK * (K_DIM / 4) + threads - 1) / threads;
        convert_hilo<<<blocksX, threads>>>(x, xc_ptr, T_TOK);
        int blocksW = (G_GRP * N_DIM * (K_DIM / 4) + threads - 1) / threads;
        convert_hilo<<<blocksW, threads>>>(w, wc_ptr, G_GRP * N_DIM);
    }

    cudaFuncSetAttribute(grouped_gemm_hmma,
                         cudaFuncAttributeMaxDynamicSharedMemorySize, SMEM_TOTAL);
    dim3 grid(N_DIM / BN, T_TOK / BM, G_GRP);   // 16 x 64 x 8
    grouped_gemm_hmma<<<grid, 256, SMEM_TOTAL>>>(offs, out);
}

// round 6
// speedup vs baseline: 6.6712x; 2.4008x over previous
#include <cuda_runtime.h>
#include <cuda_fp16.h>
#include <cstdint>

// ---------------- problem constants ----------------
#define T_TOK 8192
#define G_GRP 8
#define K_DIM 1024
#define N_DIM 2048

// ---------------- scratch (fp16) ----------------
__device__ __half g_xh[(size_t)T_TOK * K_DIM];            // [T, 1024]  16MB
__device__ __half g_wh[(size_t)G_GRP * N_DIM * K_DIM];    // [G*N, 1024] 32MB

// ---------------- conversion kernel (x and w in one launch) ----------------
__global__ void convert_fp16(const float* __restrict__ x,
                             const float* __restrict__ w)
{
    const size_t XE = (size_t)T_TOK * K_DIM;                 // 8.39M (mult of 8)
    const size_t WE = (size_t)G_GRP * N_DIM * K_DIM;         // 16.8M
    size_t i = ((size_t)blockIdx.x * blockDim.x + threadIdx.x) * 8;
    const float* src;
    __half* dst;
    size_t off;
    if (i < XE) { src = x; dst = g_xh; off = i; }
    else        { off = i - XE; if (off >= WE) return; src = w; dst = g_wh; }
    const float4 v0 = *reinterpret_cast<const float4*>(src + off);
    const float4 v1 = *reinterpret_cast<const float4*>(src + off + 4);
    union { __half h[8]; uint4 u; } P;
    P.h[0] = __float2half_rn(v0.x); P.h[1] = __float2half_rn(v0.y);
    P.h[2] = __float2half_rn(v0.z); P.h[3] = __float2half_rn(v0.w);
    P.h[4] = __float2half_rn(v1.x); P.h[5] = __float2half_rn(v1.y);
    P.h[6] = __float2half_rn(v1.z); P.h[7] = __float2half_rn(v1.w);
    *reinterpret_cast<uint4*>(dst + off) = P.u;
}

// ---------------- PTX helpers (baseline features only) ----------------
__device__ __forceinline__ uint32_t smem_u32(const void* p) {
    uint32_t a;
    asm("{ .reg .u64 t; cvta.to.shared.u64 t, %1; cvt.u32.u64 %0, t; }"
        : "=r"(a) : "l"(p));
    return a;
}
__device__ __forceinline__ void cp16(uint32_t dst, const void* src) {
    asm volatile("cp.async.cg.shared.global [%0], [%1], 16;" :: "r"(dst), "l"(src));
}
#define CP_COMMIT() asm volatile("cp.async.commit_group;" ::: "memory")
#define CP_WAIT1()  asm volatile("cp.async.wait_group 1;" ::: "memory")

__device__ __forceinline__ void ldsm_x4(uint32_t& r0, uint32_t& r1,
                                        uint32_t& r2, uint32_t& r3, uint32_t a) {
    asm volatile("ldmatrix.sync.aligned.m8n8.x4.shared.b16 {%0,%1,%2,%3}, [%4];"
                 : "=r"(r0), "=r"(r1), "=r"(r2), "=r"(r3) : "r"(a));
}
__device__ __forceinline__ void mma_16816(float* c, const uint32_t* a,
                                          const uint32_t* b) {
    asm volatile(
        "mma.sync.aligned.m16n8k16.row.col.f32.f16.f16.f32 "
        "{%0,%1,%2,%3}, {%4,%5,%6,%7}, {%8,%9}, {%0,%1,%2,%3};"
        : "+f"(c[0]), "+f"(c[1]), "+f"(c[2]), "+f"(c[3])
        : "r"(a[0]), "r"(a[1]), "r"(a[2]), "r"(a[3]), "r"(b[0]), "r"(b[1]));
}

// ---------------- GEMM kernel ----------------
// BK=64 fp16 = 128 bytes per smem row (perfect SW128 fit).
constexpr int BM = 128, BN = 128, BK = 64;
constexpr int TILE = BM * 128;                    // 16384 bytes (A or B tile)
constexpr int STAGE_BYTES = 2 * TILE;             // 32768
constexpr int STAGES = 3;
constexpr int SMEM_TOTAL = STAGES * STAGE_BYTES;  // 98304 -> 2 CTAs/SM
constexpr int NITER = K_DIM / BK;                 // 16

// sw128 swizzle for 128-byte rows: 16B chunk c at row r lands at chunk c^(r&7)
__device__ __forceinline__ uint32_t swz(uint32_t row, uint32_t chunk) {
    return row * 128u + ((chunk ^ (row & 7u)) << 4);
}

__global__ __launch_bounds__(256, 2)
void grouped_gemm_hmma(const int* __restrict__ offs, float* __restrict__ out)
{
    const int g = blockIdx.z;
    const int lo = (g == 0) ? 0 : __ldg(offs + g - 1);
    const int hi = __ldg(offs + g);
    const int m0 = blockIdx.y * BM;
    if (hi <= m0 || lo >= m0 + BM) return;   // ghost block
    const int n0 = blockIdx.x * BN;

    extern __shared__ __align__(1024) char smem[];
    const uint32_t sb = smem_u32(smem);

    const int tid  = threadIdx.x;
    const int wid  = tid >> 5;
    const int lane = tid & 31;

    // warp grid 2 (m) x 4 (n): warp tile 64x32
    const int WM0 = (wid >> 2) * 64;
    const int WN0 = (wid & 3) * 32;

    // ---- cp.async mapping: per tile 128 rows x 8 chunks = 1024; A+B = 8/thread
    const int c8 = tid & 7;
    const int r0 = tid >> 3;
    const __half* aG = g_xh + (size_t)(m0 + r0) * K_DIM + c8 * 8;
    const __half* bG = g_wh + ((size_t)g * N_DIM + n0 + r0) * K_DIM + c8 * 8;

    auto load_stage = [&](int s) {
        const int kb = s * BK;
        const uint32_t base = sb + (uint32_t)(s % STAGES) * STAGE_BYTES;
#pragma unroll
        for (int j = 0; j < 4; j++) {
            const uint32_t row = (uint32_t)r0 + 32u * j;
            const uint32_t so  = swz(row, c8);
            cp16(base + so,        aG + (size_t)(32 * j) * K_DIM + kb);
            cp16(base + TILE + so, bG + (size_t)(32 * j) * K_DIM + kb);
        }
    };

    float acc[4][4][4];
#pragma unroll
    for (int i = 0; i < 4; i++)
#pragma unroll
        for (int j = 0; j < 4; j++)
#pragma unroll
            for (int q = 0; q < 4; q++) acc[i][j][q] = 0.0f;

    load_stage(0); CP_COMMIT();
    load_stage(1); CP_COMMIT();

    for (int it = 0; it < NITER; it++) {
        CP_WAIT1();          // stage `it` resident
        __syncthreads();     // all warps done with buf (it+2)%3 (= it-1)

        if (it + 2 < NITER) load_stage(it + 2);
        CP_COMMIT();         // unconditional: uniform group counting

        const uint32_t aT = sb + (uint32_t)(it % STAGES) * STAGE_BYTES;
        const uint32_t bT = aT + TILE;

#pragma unroll
        for (int ks = 0; ks < BK / 16; ks++) {   // 4 k16 steps
            const uint32_t cA = 2u * ks;
            uint32_t a[4][4], b[4][2];
#pragma unroll
            for (int i = 0; i < 4; i++) {
                const uint32_t row = (uint32_t)(WM0 + i * 16 + (lane & 15));
                const uint32_t ch  = cA + (uint32_t)(lane >> 4);
                ldsm_x4(a[i][0], a[i][1], a[i][2], a[i][3], aT + swz(row, ch));
            }
#pragma unroll
            for (int jp = 0; jp < 2; jp++) {     // x4 covers a j-pair
                const uint32_t row = (uint32_t)(WN0 + (jp * 2 + ((lane >> 4) & 1)) * 8
                                                + (lane & 7));
                const uint32_t ch  = cA + ((uint32_t)(lane >> 3) & 1u);
                ldsm_x4(b[jp * 2][0], b[jp * 2][1],
                        b[jp * 2 + 1][0], b[jp * 2 + 1][1], bT + swz(row, ch));
            }
#pragma unroll
            for (int i = 0; i < 4; i++)
#pragma unroll
                for (int j = 0; j < 4; j++)
                    mma_16816(acc[i][j], a[i], b[j]);
        }
    }

    // ---- epilogue: direct fp32 stores with group row-clipping ----
    const int rbase = m0 + WM0 + (lane >> 2);
    const int cbase = n0 + WN0 + (lane & 3) * 2;
#pragma unroll
    for (int i = 0; i < 4; i++) {
        const int ra = rbase + i * 16;
        const int rb = ra + 8;
        const bool wa = (ra >= lo && ra < hi);
        const bool wb = (rb >= lo && rb < hi);
        float* pa = out + (size_t)ra * N_DIM + cbase;
        float* pb = out + (size_t)rb * N_DIM + cbase;
#pragma unroll
        for (int j = 0; j < 4; j++) {
            if (wa) *reinterpret_cast<float2*>(pa + j * 8) =
                make_float2(acc[i][j][0], acc[i][j][1]);
            if (wb) *reinterpret_cast<float2*>(pb + j * 8) =
                make_float2(acc[i][j][2], acc[i][j][3]);
        }
    }
}

// ---------------- launch ----------------
extern "C" void kernel_launch(void* const* d_in, const int* in_sizes, int n_in,
                              void* d_out, int out_size) {
    const float* x    = (const float*)d_in[0];  // [T, K]
    const float* w    = (const float*)d_in[1];  // [G, N, K]
    const int*   offs = (const int*)d_in[2];    // [G]
    float* out = (float*)d_out;                 // [T, N]

    // single conversion launch covering x then w (both counts divisible by 8)
    {
        const size_t total8 = ((size_t)T_TOK * K_DIM + (size_t)G_GRP * N_DIM * K_DIM) / 8;
        const int threads = 256;
        const int blocks = (int)((total8 + threads - 1) / threads);  // 12288
        convert_fp16<<<blocks, threads>>>(x, w);
    }

    cudaFuncSetAttribute(grouped_gemm_hmma,
                         cudaFuncAttributeMaxDynamicSharedMemorySize, SMEM_TOTAL);
    dim3 grid(N_DIM / BN, T_TOK / BM, G_GRP);   // 16 x 64 x 8
    grouped_gemm_hmma<<<grid, 256, SMEM_TOTAL>>>(offs, out);
}